// round 12
// baseline (speedup 1.0000x reference)
#include <cuda_runtime.h>
#include <cuda_fp16.h>
#include <cstdint>
#include <cstring>

// ---------------- Problem constants ----------------
#define BATCH   8192
#define IN_CH   64
#define XCOLS   1728           // 27*64
#define OUTCOLS 12544          // 49*256
#define ROWS    49
#define CH      256
#define KTOT    192            // 3*64
#define CHUNKS  3
#define KC      64             // K (halves) per chunk == one board cell
#define BM      64
#define BN      128            // per-CTA column half
#define NTHREADS 256
#define NGRP    6              // batch-tile groups per (line, half)

// SMEM: fp16 rows of 64 data halves padded to 72 (144B) -> conflict-free ldmatrix
#define RSH       72
#define ROWB      (RSH * 2)                    // 144 bytes per row
#define A_CHUNK   (BM * ROWB)                  // 9216
#define B_CHUNK   (BN * ROWB)                  // 18432
#define A_BUF     (CHUNKS * A_CHUNK)           // 27648
#define OFF_B     (2 * A_BUF)                  // 55296
#define SMEM_TOTAL (OFF_B + CHUNKS * B_CHUNK)  // 110592 (108KB -> 2 CTAs/SM)

__device__ int    d_cell[ROWS * 3];
__device__ __align__(16) __half d_xH[(size_t)BATCH * XCOLS];        // 28.3MB
__device__ __align__(16) __half d_vTH[(size_t)ROWS * CH * KTOT];    // 4.8MB, [r][perm(n)][k]

// ---------------- helpers ----------------
__device__ __forceinline__ uint32_t h2_as_u32(__half2 h) {
    uint32_t u;
    memcpy(&u, &h, 4);
    return u;
}
__device__ __forceinline__ uint32_t smem_u32(const void* p) {
    uint32_t a;
    asm("{ .reg .u64 t; cvta.to.shared.u64 t, %1; cvt.u32.u64 %0, t; }" : "=r"(a) : "l"(p));
    return a;
}
__device__ __forceinline__ void cp_async16(uint32_t dst, const void* src) {
    asm volatile("cp.async.cg.shared.global [%0], [%1], 16;"
                 :: "r"(dst), "l"(__cvta_generic_to_global(src)) : "memory");
}
#define CP_COMMIT() asm volatile("cp.async.commit_group;" ::: "memory")
#define CP_WAIT(n)  asm volatile("cp.async.wait_group %0;" :: "n"(n) : "memory")

__device__ __forceinline__ void ldmx4(uint32_t* r, uint32_t addr) {
    asm volatile("ldmatrix.sync.aligned.m8n8.x4.shared.b16 {%0,%1,%2,%3}, [%4];"
                 : "=r"(r[0]), "=r"(r[1]), "=r"(r[2]), "=r"(r[3]) : "r"(addr));
}
__device__ __forceinline__ void mma_f16(float* c, const uint32_t* a, const uint32_t* b) {
    asm volatile(
        "mma.sync.aligned.m16n8k16.row.col.f32.f16.f16.f32 "
        "{%0,%1,%2,%3}, {%4,%5,%6,%7}, {%8,%9}, {%0,%1,%2,%3};"
        : "+f"(c[0]), "+f"(c[1]), "+f"(c[2]), "+f"(c[3])
        : "r"(a[0]), "r"(a[1]), "r"(a[2]), "r"(a[3]), "r"(b[0]), "r"(b[1]));
}

// Column permutation: phys col n stored at MMA n-position perm(n) so that
// adjacent nt-fragment pairs hold 4 consecutive phys columns per lane quad.
// Stays within each 16-col block, so the 128-col halves are preserved.
__device__ __forceinline__ int permN(int n) {
    const int q = (n & 15) >> 2, h = (n >> 1) & 1, b = n & 1;
    return (n & ~15) | (h << 3) | (q << 1) | b;
}

// ---------------- single merged pre-pass ----------------
__global__ void prepass_kernel(const float* __restrict__ x,
                               const float* __restrict__ v) {
    if (blockIdx.x == 0 && threadIdx.x == 0) {
        int col = 0, step = 0, xx, yy, zz;
#define PUT(X, Y, Z) do { d_cell[col*3 + step] = (X) + 3*(Y) + 9*(Z); \
                          step = (step + 1) % 3; } while (0)
        for (xx = 0; xx < 3; xx++) {
            for (yy = 0; yy < 3; yy++) { for (zz = 0; zz < 3; zz++) PUT(xx,yy,zz); col++; }
            for (zz = 0; zz < 3; zz++) { for (yy = 0; yy < 3; yy++) PUT(xx,yy,zz); col++; }
            for (yy = 0; yy < 3; yy++) { zz = yy;     PUT(xx,yy,zz); } col++;
            for (yy = 0; yy < 3; yy++) { zz = 2 - yy; PUT(xx,yy,zz); } col++;
        }
        for (zz = 0; zz < 3; zz++) {
            for (yy = 0; yy < 3; yy++) { for (xx = 0; xx < 3; xx++) PUT(xx,yy,zz); col++; }
            for (yy = 0; yy < 3; yy++) { xx = yy;     PUT(xx,yy,zz); } col++;
            for (yy = 0; yy < 3; yy++) { xx = 2 - yy; PUT(xx,yy,zz); } col++;
        }
        for (yy = 0; yy < 3; yy++) {
            for (zz = 0; zz < 3; zz++) { xx = zz;     PUT(xx,yy,zz); } col++;
            for (zz = 0; zz < 3; zz++) { xx = 2 - zz; PUT(xx,yy,zz); } col++;
        }
        for (xx = 0; xx < 3; xx++) { yy = xx;     zz = xx;     PUT(xx,yy,zz); } col++;
        for (xx = 0; xx < 3; xx++) { yy = 2 - xx; zz = 2 - xx; PUT(xx,yy,zz); } col++;
        for (xx = 0; xx < 3; xx++) { yy = xx;     zz = 2 - xx; PUT(xx,yy,zz); } col++;
        for (xx = 0; xx < 3; xx++) { zz = xx;     yy = 2 - xx; PUT(xx,yy,zz); } col++;
#undef PUT
    }

    if (blockIdx.x < ROWS) {
        const int r = blockIdx.x;
        const float* vb = v + (size_t)r * CH;
        __half* dst = d_vTH + (size_t)r * CH * KTOT;
        for (int u = threadIdx.x; u < CH * (KTOT / 8); u += blockDim.x) {
            const int n  = u & (CH - 1);
            const int k8 = u >> 8;
            uint4 o;
            uint32_t h[4];
#pragma unroll
            for (int p = 0; p < 4; p++) {
                float lo = vb[(size_t)(k8 * 8 + 2 * p + 0) * OUTCOLS + n];
                float hi = vb[(size_t)(k8 * 8 + 2 * p + 1) * OUTCOLS + n];
                h[p] = h2_as_u32(__floats2half2_rn(lo, hi));
            }
            o.x = h[0]; o.y = h[1]; o.z = h[2]; o.w = h[3];
            *reinterpret_cast<uint4*>(dst + (size_t)permN(n) * KTOT + k8 * 8) = o;
        }
    }

    const size_t n8 = (size_t)BATCH * XCOLS / 8;
    const float4* src = reinterpret_cast<const float4*>(x);
    uint4* dst = reinterpret_cast<uint4*>(d_xH);
    for (size_t i = blockIdx.x * (size_t)blockDim.x + threadIdx.x;
         i < n8; i += (size_t)gridDim.x * blockDim.x) {
        float4 a = src[2 * i], b = src[2 * i + 1];
        uint4 o;
        o.x = h2_as_u32(__floats2half2_rn(a.x, a.y));
        o.y = h2_as_u32(__floats2half2_rn(a.z, a.w));
        o.z = h2_as_u32(__floats2half2_rn(b.x, b.y));
        o.w = h2_as_u32(__floats2half2_rn(b.z, b.w));
        dst[i] = o;
    }
}

// ---------------- main GEMM: N-split, 2 CTAs/SM, folded epilogue ----------------
__global__ void __launch_bounds__(NTHREADS, 2)
tic_mma_kernel(const float* __restrict__ bias, float* __restrict__ out) {
    extern __shared__ char smem[];
    const uint32_t sb = smem_u32(smem);

    const int g    = blockIdx.x >> 1;    // 0..5  batch group
    const int half = blockIdx.x & 1;     // 0..1  column half
    const int r    = blockIdx.y;         // 0..48

    // 128 tiles of 64 rows per line: g<2 -> 22 tiles, else 21
    const int nbt   = (g < 2) ? 22 : 21;
    const int btsta = g * 21 + min(g, 2);

    const int tid = threadIdx.x;
    const int wid = tid >> 5, lid = tid & 31;
    const int wr = wid >> 2, wc = wid & 3;          // 2 x 4 warps; warp tile 32x32
    const int grp = lid >> 3, lr = lid & 7;

    const __half* vTb = d_vTH + (size_t)r * CH * KTOT + (size_t)half * BN * KTOT;

    const int ld_row = tid >> 3;          // 0..31
    const int ld_f4  = tid & 7;

    const uint32_t aBase = ((wr * 32 + ((grp & 1) << 3) + lr) * RSH + ((grp >> 1) << 3)) * 2;
    const uint32_t bBase = ((wc * 32 + ((grp & 1) << 3) + lr) * RSH + ((grp >> 1) << 3)) * 2;

    // ---- prologue: B (3 chunks, this half) + A(bt0), one commit group ----
#pragma unroll
    for (int c = 0; c < CHUNKS; c++) {
        const uint32_t sB = sb + OFF_B + c * B_CHUNK;
#pragma unroll
        for (int it = 0; it < 4; it++) {
            const int n = ld_row + it * 32;
            cp_async16(sB + n * ROWB + ld_f4 * 16,
                       vTb + (size_t)n * KTOT + c * KC + ld_f4 * 8);
        }
    }
    {
        const __half* xb = d_xH + (size_t)btsta * BM * XCOLS;
#pragma unroll
        for (int c = 0; c < CHUNKS; c++) {
            const uint32_t sA = sb + c * A_CHUNK;
            const int cellbase = d_cell[r * 3 + c] * IN_CH;
#pragma unroll
            for (int it = 0; it < 2; it++) {
                const int row = ld_row + it * 32;
                cp_async16(sA + row * ROWB + ld_f4 * 16,
                           xb + (size_t)row * XCOLS + cellbase + ld_f4 * 8);
            }
        }
    }
    CP_COMMIT();

    const int colw = r * CH + half * BN + wc * 32;
    const int q4   = 4 * (lid & 3);
    const int rbase = wr * 32 + (lid >> 2);

    float4 bj[2];
#pragma unroll
    for (int j = 0; j < 2; j++)
        bj[j] = *reinterpret_cast<const float4*>(bias + colw + 16 * j + q4);

    float accA[2][4][4], accB[2][4][4];
    uint32_t af[2][2][4], bf[2][4][2];

#define LDFRAG(S, FB, ABUF) do {                                               \
        const int c_ = (S) >> 2, ks_ = (S) & 3;                                \
        const uint32_t sA_ = (ABUF) + c_ * A_CHUNK;                            \
        const uint32_t sB_ = sb + OFF_B + c_ * B_CHUNK;                        \
        _Pragma("unroll")                                                      \
        for (int mt = 0; mt < 2; mt++)                                         \
            ldmx4(af[FB][mt], sA_ + aBase + mt * 16 * ROWB + ks_ * 32);        \
        _Pragma("unroll")                                                      \
        for (int np = 0; np < 2; np++) {                                       \
            uint32_t t[4];                                                     \
            ldmx4(t, sB_ + bBase + np * 16 * ROWB + ks_ * 32);                 \
            bf[FB][np * 2 + 0][0] = t[0]; bf[FB][np * 2 + 0][1] = t[2];        \
            bf[FB][np * 2 + 1][0] = t[1]; bf[FB][np * 2 + 1][1] = t[3];        \
        } } while (0)

    // one bias-added float4 store of PRV tile, K in [0,8)
#define STORE_K(PRV, BTP, K) do {                                              \
        const int j_ = (K) >> 2, mt_ = ((K) >> 1) & 1, hf_ = (K) & 1;          \
        const float* e_ = PRV[mt_][2 * j_];                                    \
        const float* o_ = PRV[mt_][2 * j_ + 1];                                \
        float* p_ = out + (size_t)((BTP) * BM + rbase + mt_ * 16 + hf_ * 8)    \
                          * OUTCOLS + colw + 16 * j_ + q4;                     \
        float4 v_;                                                             \
        if ((hf_) == 0) { v_.x = e_[0] + bj[j_].x; v_.y = e_[1] + bj[j_].y;    \
                          v_.z = o_[0] + bj[j_].z; v_.w = o_[1] + bj[j_].w; }  \
        else            { v_.x = e_[2] + bj[j_].x; v_.y = e_[3] + bj[j_].y;    \
                          v_.z = o_[2] + bj[j_].z; v_.w = o_[3] + bj[j_].w; }  \
        *reinterpret_cast<float4*>(p_) = v_;                                   \
    } while (0)

#define DO_ITER(CUR, PRV, I) do {                                              \
        const int bt_ = btsta + (I);                                           \
        CP_WAIT(0);                                                            \
        __syncthreads();                                                       \
        if ((I) + 1 < nbt) {                                                   \
            const __half* xb_ = d_xH + (size_t)(bt_ + 1) * BM * XCOLS;         \
            const uint32_t bufn_ = (((I) + 1) & 1) * A_BUF;                    \
            _Pragma("unroll")                                                  \
            for (int c = 0; c < CHUNKS; c++) {                                 \
                const uint32_t sA_ = sb + bufn_ + c * A_CHUNK;                 \
                const int cb_ = d_cell[r * 3 + c] * IN_CH;                     \
                _Pragma("unroll")                                              \
                for (int it = 0; it < 2; it++) {                               \
                    const int row_ = ld_row + it * 32;                         \
                    cp_async16(sA_ + row_ * ROWB + ld_f4 * 16,                 \
                               xb_ + (size_t)row_ * XCOLS + cb_ + ld_f4 * 8);  \
                }                                                              \
            }                                                                  \
            CP_COMMIT();                                                       \
        }                                                                      \
        _Pragma("unroll")                                                      \
        for (int a_ = 0; a_ < 2; a_++)                                         \
            _Pragma("unroll")                                                  \
            for (int b_ = 0; b_ < 4; b_++)                                     \
                _Pragma("unroll")                                              \
                for (int q_ = 0; q_ < 4; q_++) CUR[a_][b_][q_] = 0.0f;         \
        const uint32_t abuf_ = sb + ((I) & 1) * A_BUF;                         \
        LDFRAG(0, 0, abuf_);                                                   \
        _Pragma("unroll")                                                      \
        for (int s = 0; s < 12; s++) {                                         \
            if (s < 11) {                                                      \
                if ((s + 1) & 1) LDFRAG(s + 1, 1, abuf_);                      \
                else             LDFRAG(s + 1, 0, abuf_);                      \
            }                                                                  \
            const int cur_ = s & 1;                                            \
            _Pragma("unroll")                                                  \
            for (int mt = 0; mt < 2; mt++)                                     \
                _Pragma("unroll")                                              \
                for (int nt = 0; nt < 4; nt++)                                 \
                    mma_f16(CUR[mt][nt], af[cur_][mt], bf[cur_][nt]);          \
            if ((I) > 0 && s < 8) STORE_K(PRV, bt_ - 1, s);                    \
        }                                                                      \
    } while (0)

    for (int i = 0; i < nbt; i++) {
        if (i & 1) DO_ITER(accB, accA, i);
        else       DO_ITER(accA, accB, i);
    }

    // drain final tile's stores
    {
        const int btl = btsta + nbt - 1;
        if ((nbt - 1) & 1) {
#pragma unroll
            for (int k = 0; k < 8; k++) STORE_K(accB, btl, k);
        } else {
#pragma unroll
            for (int k = 0; k < 8; k++) STORE_K(accA, btl, k);
        }
    }
#undef DO_ITER
#undef STORE_K
#undef LDFRAG
}

extern "C" void kernel_launch(void* const* d_in, const int* in_sizes, int n_in,
                              void* d_out, int out_size) {
    const float* x = nullptr;
    const float* v = nullptr;
    const float* b = nullptr;
    for (int i = 0; i < n_in; i++) {
        if (in_sizes[i] == BATCH * XCOLS)            x = (const float*)d_in[i];
        else if (in_sizes[i] == 3 * IN_CH * OUTCOLS) v = (const float*)d_in[i];
        else if (in_sizes[i] == OUTCOLS)             b = (const float*)d_in[i];
    }
    float* out = (float*)d_out;

    cudaFuncSetAttribute(tic_mma_kernel,
                         cudaFuncAttributeMaxDynamicSharedMemorySize, SMEM_TOTAL);

    prepass_kernel<<<2048, 256>>>(x, v);

    dim3 grid(2 * NGRP, ROWS);   // (12, 49) = 588 CTAs, 2 CTAs/SM, ~2 waves
    tic_mma_kernel<<<grid, NTHREADS, SMEM_TOTAL>>>(b, out);
}

// round 13
// speedup vs baseline: 1.0663x; 1.0663x over previous
#include <cuda_runtime.h>
#include <cuda_fp16.h>
#include <cstdint>
#include <cstring>

// ---------------- Problem constants ----------------
#define BATCH   8192
#define IN_CH   64
#define XCOLS   1728           // 27*64
#define OUTCOLS 12544          // 49*256
#define ROWS    49
#define CH      256
#define KTOT    192            // 3*64
#define CHUNKS  3
#define KC      64             // K (halves) per chunk == one board cell
#define BM      64
#define BN      128            // per-CTA column half
#define NTHREADS 128
#define NGRP    6              // batch-tile groups per (line, half)

// SMEM: fp16 rows of 64 data halves padded to 72 (144B) -> conflict-free ldmatrix
#define RSH       72
#define ROWB      (RSH * 2)                    // 144 bytes per row
#define A_CHUNK   (BM * ROWB)                  // 9216
#define B_CHUNK   (BN * ROWB)                  // 18432
#define A_BUF     (CHUNKS * A_CHUNK)           // 27648
#define OFF_B     (2 * A_BUF)                  // 55296
#define SMEM_TOTAL (OFF_B + CHUNKS * B_CHUNK)  // 110592 (108KB -> 2 CTAs/SM)

__device__ int    d_cell[ROWS * 3];
__device__ __align__(16) __half d_xH[(size_t)BATCH * XCOLS];        // 28.3MB
__device__ __align__(16) __half d_vTH[(size_t)ROWS * CH * KTOT];    // 4.8MB, [r][perm(n)][k]

// ---------------- helpers ----------------
__device__ __forceinline__ uint32_t h2_as_u32(__half2 h) {
    uint32_t u;
    memcpy(&u, &h, 4);
    return u;
}
__device__ __forceinline__ uint32_t smem_u32(const void* p) {
    uint32_t a;
    asm("{ .reg .u64 t; cvta.to.shared.u64 t, %1; cvt.u32.u64 %0, t; }" : "=r"(a) : "l"(p));
    return a;
}
__device__ __forceinline__ void cp_async16(uint32_t dst, const void* src) {
    asm volatile("cp.async.cg.shared.global [%0], [%1], 16;"
                 :: "r"(dst), "l"(__cvta_generic_to_global(src)) : "memory");
}
#define CP_COMMIT() asm volatile("cp.async.commit_group;" ::: "memory")
#define CP_WAIT(n)  asm volatile("cp.async.wait_group %0;" :: "n"(n) : "memory")

__device__ __forceinline__ void ldmx4(uint32_t* r, uint32_t addr) {
    asm volatile("ldmatrix.sync.aligned.m8n8.x4.shared.b16 {%0,%1,%2,%3}, [%4];"
                 : "=r"(r[0]), "=r"(r[1]), "=r"(r[2]), "=r"(r[3]) : "r"(addr));
}
__device__ __forceinline__ void mma_f16(float* c, const uint32_t* a, const uint32_t* b) {
    asm volatile(
        "mma.sync.aligned.m16n8k16.row.col.f32.f16.f16.f32 "
        "{%0,%1,%2,%3}, {%4,%5,%6,%7}, {%8,%9}, {%0,%1,%2,%3};"
        : "+f"(c[0]), "+f"(c[1]), "+f"(c[2]), "+f"(c[3])
        : "r"(a[0]), "r"(a[1]), "r"(a[2]), "r"(a[3]), "r"(b[0]), "r"(b[1]));
}

// Column permutation: phys col n stored at MMA n-position perm(n) so that
// adjacent nt-fragment pairs hold 4 consecutive phys columns per lane quad.
// Stays within each 16-col block, so the 128-col halves are preserved.
__device__ __forceinline__ int permN(int n) {
    const int q = (n & 15) >> 2, h = (n >> 1) & 1, b = n & 1;
    return (n & ~15) | (h << 3) | (q << 1) | b;
}

// ---------------- single merged pre-pass ----------------
__global__ void prepass_kernel(const float* __restrict__ x,
                               const float* __restrict__ v) {
    if (blockIdx.x == 0 && threadIdx.x == 0) {
        int col = 0, step = 0, xx, yy, zz;
#define PUT(X, Y, Z) do { d_cell[col*3 + step] = (X) + 3*(Y) + 9*(Z); \
                          step = (step + 1) % 3; } while (0)
        for (xx = 0; xx < 3; xx++) {
            for (yy = 0; yy < 3; yy++) { for (zz = 0; zz < 3; zz++) PUT(xx,yy,zz); col++; }
            for (zz = 0; zz < 3; zz++) { for (yy = 0; yy < 3; yy++) PUT(xx,yy,zz); col++; }
            for (yy = 0; yy < 3; yy++) { zz = yy;     PUT(xx,yy,zz); } col++;
            for (yy = 0; yy < 3; yy++) { zz = 2 - yy; PUT(xx,yy,zz); } col++;
        }
        for (zz = 0; zz < 3; zz++) {
            for (yy = 0; yy < 3; yy++) { for (xx = 0; xx < 3; xx++) PUT(xx,yy,zz); col++; }
            for (yy = 0; yy < 3; yy++) { xx = yy;     PUT(xx,yy,zz); } col++;
            for (yy = 0; yy < 3; yy++) { xx = 2 - yy; PUT(xx,yy,zz); } col++;
        }
        for (yy = 0; yy < 3; yy++) {
            for (zz = 0; zz < 3; zz++) { xx = zz;     PUT(xx,yy,zz); } col++;
            for (zz = 0; zz < 3; zz++) { xx = 2 - zz; PUT(xx,yy,zz); } col++;
        }
        for (xx = 0; xx < 3; xx++) { yy = xx;     zz = xx;     PUT(xx,yy,zz); } col++;
        for (xx = 0; xx < 3; xx++) { yy = 2 - xx; zz = 2 - xx; PUT(xx,yy,zz); } col++;
        for (xx = 0; xx < 3; xx++) { yy = xx;     zz = 2 - xx; PUT(xx,yy,zz); } col++;
        for (xx = 0; xx < 3; xx++) { zz = xx;     yy = 2 - xx; PUT(xx,yy,zz); } col++;
#undef PUT
    }

    if (blockIdx.x < ROWS) {
        const int r = blockIdx.x;
        const float* vb = v + (size_t)r * CH;
        __half* dst = d_vTH + (size_t)r * CH * KTOT;
        for (int u = threadIdx.x; u < CH * (KTOT / 8); u += blockDim.x) {
            const int n  = u & (CH - 1);
            const int k8 = u >> 8;
            uint4 o;
            uint32_t h[4];
#pragma unroll
            for (int p = 0; p < 4; p++) {
                float lo = vb[(size_t)(k8 * 8 + 2 * p + 0) * OUTCOLS + n];
                float hi = vb[(size_t)(k8 * 8 + 2 * p + 1) * OUTCOLS + n];
                h[p] = h2_as_u32(__floats2half2_rn(lo, hi));
            }
            o.x = h[0]; o.y = h[1]; o.z = h[2]; o.w = h[3];
            *reinterpret_cast<uint4*>(dst + (size_t)permN(n) * KTOT + k8 * 8) = o;
        }
    }

    const size_t n8 = (size_t)BATCH * XCOLS / 8;
    const float4* src = reinterpret_cast<const float4*>(x);
    uint4* dst = reinterpret_cast<uint4*>(d_xH);
    for (size_t i = blockIdx.x * (size_t)blockDim.x + threadIdx.x;
         i < n8; i += (size_t)gridDim.x * blockDim.x) {
        float4 a = src[2 * i], b = src[2 * i + 1];
        uint4 o;
        o.x = h2_as_u32(__floats2half2_rn(a.x, a.y));
        o.y = h2_as_u32(__floats2half2_rn(a.z, a.w));
        o.z = h2_as_u32(__floats2half2_rn(b.x, b.y));
        o.w = h2_as_u32(__floats2half2_rn(b.z, b.w));
        dst[i] = o;
    }
}

// ---------------- main GEMM: 4 warps, 32x64 warp tile, 2 CTAs/SM ----------------
__global__ void __launch_bounds__(NTHREADS, 2)
tic_mma_kernel(const float* __restrict__ bias, float* __restrict__ out) {
    extern __shared__ char smem[];
    const uint32_t sb = smem_u32(smem);

    const int g    = blockIdx.x >> 1;    // 0..5  batch group
    const int half = blockIdx.x & 1;     // 0..1  column half
    const int r    = blockIdx.y;         // 0..48

    // 128 tiles of 64 rows per line: g<2 -> 22 tiles, else 21
    const int nbt   = (g < 2) ? 22 : 21;
    const int btsta = g * 21 + min(g, 2);

    const int tid = threadIdx.x;
    const int wid = tid >> 5, lid = tid & 31;
    const int wr = wid >> 1, wc = wid & 1;          // 2 x 2 warps; warp tile 32x64
    const int grp = lid >> 3, lr = lid & 7;

    const __half* vTb = d_vTH + (size_t)r * CH * KTOT + (size_t)half * BN * KTOT;

    const int ld_row = tid >> 3;          // 0..15
    const int ld_f4  = tid & 7;

    const uint32_t aBase = ((wr * 32 + ((grp & 1) << 3) + lr) * RSH + ((grp >> 1) << 3)) * 2;
    const uint32_t bBase = ((wc * 64 + ((grp & 1) << 3) + lr) * RSH + ((grp >> 1) << 3)) * 2;

    // ---- prologue: B (3 chunks, this half) + A(bt0), one commit group ----
#pragma unroll
    for (int c = 0; c < CHUNKS; c++) {
        const uint32_t sB = sb + OFF_B + c * B_CHUNK;
#pragma unroll
        for (int it = 0; it < 8; it++) {
            const int n = ld_row + it * 16;
            cp_async16(sB + n * ROWB + ld_f4 * 16,
                       vTb + (size_t)n * KTOT + c * KC + ld_f4 * 8);
        }
    }
    {
        const __half* xb = d_xH + (size_t)btsta * BM * XCOLS;
#pragma unroll
        for (int c = 0; c < CHUNKS; c++) {
            const uint32_t sA = sb + c * A_CHUNK;
            const int cellbase = d_cell[r * 3 + c] * IN_CH;
#pragma unroll
            for (int it = 0; it < 4; it++) {
                const int row = ld_row + it * 16;
                cp_async16(sA + row * ROWB + ld_f4 * 16,
                           xb + (size_t)row * XCOLS + cellbase + ld_f4 * 8);
            }
        }
    }
    CP_COMMIT();

    const int colw = r * CH + half * BN + wc * 64;
    const int q4   = 4 * (lid & 3);
    const int rbase = wr * 32 + (lid >> 2);

    float4 bj[4];
#pragma unroll
    for (int j = 0; j < 4; j++)
        bj[j] = *reinterpret_cast<const float4*>(bias + colw + 16 * j + q4);

    float accA[2][8][4], accB[2][8][4];
    uint32_t af[2][2][4], bf[2][8][2];

#define LDFRAG(S, FB, ABUF) do {                                               \
        const int c_ = (S) >> 2, ks_ = (S) & 3;                                \
        const uint32_t sA_ = (ABUF) + c_ * A_CHUNK;                            \
        const uint32_t sB_ = sb + OFF_B + c_ * B_CHUNK;                        \
        _Pragma("unroll")                                                      \
        for (int mt = 0; mt < 2; mt++)                                         \
            ldmx4(af[FB][mt], sA_ + aBase + mt * 16 * ROWB + ks_ * 32);        \
        _Pragma("unroll")                                                      \
        for (int np = 0; np < 4; np++) {                                       \
            uint32_t t[4];                                                     \
            ldmx4(t, sB_ + bBase + np * 16 * ROWB + ks_ * 32);                 \
            bf[FB][np * 2 + 0][0] = t[0]; bf[FB][np * 2 + 0][1] = t[2];        \
            bf[FB][np * 2 + 1][0] = t[1]; bf[FB][np * 2 + 1][1] = t[3];        \
        } } while (0)

    // one bias-added float4 store of PRV tile, K in [0,16)
#define STORE_K(PRV, BTP, K) do {                                              \
        const int j_ = (K) >> 2, mt_ = ((K) >> 1) & 1, hf_ = (K) & 1;          \
        const float* e_ = PRV[mt_][2 * j_];                                    \
        const float* o_ = PRV[mt_][2 * j_ + 1];                                \
        float* p_ = out + (size_t)((BTP) * BM + rbase + mt_ * 16 + hf_ * 8)    \
                          * OUTCOLS + colw + 16 * j_ + q4;                     \
        float4 v_;                                                             \
        if ((hf_) == 0) { v_.x = e_[0] + bj[j_].x; v_.y = e_[1] + bj[j_].y;    \
                          v_.z = o_[0] + bj[j_].z; v_.w = o_[1] + bj[j_].w; }  \
        else            { v_.x = e_[2] + bj[j_].x; v_.y = e_[3] + bj[j_].y;    \
                          v_.z = o_[2] + bj[j_].z; v_.w = o_[3] + bj[j_].w; }  \
        *reinterpret_cast<float4*>(p_) = v_;                                   \
    } while (0)

#define DO_ITER(CUR, PRV, I) do {                                              \
        const int bt_ = btsta + (I);                                           \
        CP_WAIT(0);                                                            \
        __syncthreads();                                                       \
        if ((I) + 1 < nbt) {                                                   \
            const __half* xb_ = d_xH + (size_t)(bt_ + 1) * BM * XCOLS;         \
            const uint32_t bufn_ = (((I) + 1) & 1) * A_BUF;                    \
            _Pragma("unroll")                                                  \
            for (int c = 0; c < CHUNKS; c++) {                                 \
                const uint32_t sA_ = sb + bufn_ + c * A_CHUNK;                 \
                const int cb_ = d_cell[r * 3 + c] * IN_CH;                     \
                _Pragma("unroll")                                              \
                for (int it = 0; it < 4; it++) {                               \
                    const int row_ = ld_row + it * 16;                         \
                    cp_async16(sA_ + row_ * ROWB + ld_f4 * 16,                 \
                               xb_ + (size_t)row_ * XCOLS + cb_ + ld_f4 * 8);  \
                }                                                              \
            }                                                                  \
            CP_COMMIT();                                                       \
        }                                                                      \
        _Pragma("unroll")                                                      \
        for (int a_ = 0; a_ < 2; a_++)                                         \
            _Pragma("unroll")                                                  \
            for (int b_ = 0; b_ < 8; b_++)                                     \
                _Pragma("unroll")                                              \
                for (int q_ = 0; q_ < 4; q_++) CUR[a_][b_][q_] = 0.0f;         \
        const uint32_t abuf_ = sb + ((I) & 1) * A_BUF;                         \
        LDFRAG(0, 0, abuf_);                                                   \
        _Pragma("unroll")                                                      \
        for (int s = 0; s < 12; s++) {                                         \
            if (s < 11) {                                                      \
                if ((s + 1) & 1) LDFRAG(s + 1, 1, abuf_);                      \
                else             LDFRAG(s + 1, 0, abuf_);                      \
            }                                                                  \
            const int cur_ = s & 1;                                            \
            _Pragma("unroll")                                                  \
            for (int mt = 0; mt < 2; mt++)                                     \
                _Pragma("unroll")                                              \
                for (int nt = 0; nt < 8; nt++)                                 \
                    mma_f16(CUR[mt][nt], af[cur_][mt], bf[cur_][nt]);          \
            if ((I) > 0 && s < 8) {                                            \
                STORE_K(PRV, bt_ - 1, 2 * s);                                  \
                STORE_K(PRV, bt_ - 1, 2 * s + 1);                              \
            }                                                                  \
        }                                                                      \
    } while (0)

    for (int i = 0; i < nbt; i++) {
        if (i & 1) DO_ITER(accB, accA, i);
        else       DO_ITER(accA, accB, i);
    }

    // drain final tile's stores
    {
        const int btl = btsta + nbt - 1;
        if ((nbt - 1) & 1) {
#pragma unroll
            for (int k = 0; k < 16; k++) STORE_K(accB, btl, k);
        } else {
#pragma unroll
            for (int k = 0; k < 16; k++) STORE_K(accA, btl, k);
        }
    }
#undef DO_ITER
#undef STORE_K
#undef LDFRAG
}

extern "C" void kernel_launch(void* const* d_in, const int* in_sizes, int n_in,
                              void* d_out, int out_size) {
    const float* x = nullptr;
    const float* v = nullptr;
    const float* b = nullptr;
    for (int i = 0; i < n_in; i++) {
        if (in_sizes[i] == BATCH * XCOLS)            x = (const float*)d_in[i];
        else if (in_sizes[i] == 3 * IN_CH * OUTCOLS) v = (const float*)d_in[i];
        else if (in_sizes[i] == OUTCOLS)             b = (const float*)d_in[i];
    }
    float* out = (float*)d_out;

    cudaFuncSetAttribute(tic_mma_kernel,
                         cudaFuncAttributeMaxDynamicSharedMemorySize, SMEM_TOTAL);

    prepass_kernel<<<2048, 256>>>(x, v);

    dim3 grid(2 * NGRP, ROWS);   // (12, 49) = 588 CTAs, 2 CTAs/SM, ~2 waves
    tic_mma_kernel<<<grid, NTHREADS, SMEM_TOTAL>>>(b, out);
}

// round 14
// speedup vs baseline: 1.0669x; 1.0006x over previous
#include <cuda_runtime.h>
#include <cuda_fp16.h>
#include <cstdint>
#include <cstring>

// ---------------- Problem constants ----------------
#define BATCH   8192
#define IN_CH   64
#define XCOLS   1728           // 27*64
#define OUTCOLS 12544          // 49*256
#define ROWS    49
#define CH      256
#define KTOT    192            // 3*64
#define CHUNKS  3
#define KC      64             // K (halves) per chunk == one board cell
#define BM      64
#define BN      128            // per-CTA column half
#define NTHREADS 256
#define NGRP    6              // batch-tile groups per (line, half)

// SMEM: fp16 rows of 64 data halves padded to 72 (144B) -> conflict-free ldmatrix
#define RSH       72
#define ROWB      (RSH * 2)                    // 144 bytes per row
#define A_CHUNK   (BM * ROWB)                  // 9216
#define B_CHUNK   (BN * ROWB)                  // 18432
#define A_BUF     (CHUNKS * A_CHUNK)           // 27648
#define OFF_B     (2 * A_BUF)                  // 55296
#define SMEM_TOTAL (OFF_B + CHUNKS * B_CHUNK)  // 110592

__device__ int    d_cell[ROWS * 3];
__device__ __align__(16) __half d_xH[(size_t)BATCH * XCOLS];        // 28.3MB
__device__ __align__(16) __half d_vTH[(size_t)ROWS * CH * KTOT];    // 4.8MB, [r][perm(n)][k]

// ---------------- helpers ----------------
__device__ __forceinline__ uint32_t h2_as_u32(__half2 h) {
    uint32_t u;
    memcpy(&u, &h, 4);
    return u;
}
__device__ __forceinline__ uint32_t smem_u32(const void* p) {
    uint32_t a;
    asm("{ .reg .u64 t; cvta.to.shared.u64 t, %1; cvt.u32.u64 %0, t; }" : "=r"(a) : "l"(p));
    return a;
}
__device__ __forceinline__ void cp_async16(uint32_t dst, const void* src) {
    asm volatile("cp.async.cg.shared.global [%0], [%1], 16;"
                 :: "r"(dst), "l"(__cvta_generic_to_global(src)) : "memory");
}
#define CP_COMMIT() asm volatile("cp.async.commit_group;" ::: "memory")
#define CP_WAIT(n)  asm volatile("cp.async.wait_group %0;" :: "n"(n) : "memory")

__device__ __forceinline__ void ldmx4(uint32_t* r, uint32_t addr) {
    asm volatile("ldmatrix.sync.aligned.m8n8.x4.shared.b16 {%0,%1,%2,%3}, [%4];"
                 : "=r"(r[0]), "=r"(r[1]), "=r"(r[2]), "=r"(r[3]) : "r"(addr));
}
__device__ __forceinline__ void mma_f16(float* c, const uint32_t* a, const uint32_t* b) {
    asm volatile(
        "mma.sync.aligned.m16n8k16.row.col.f32.f16.f16.f32 "
        "{%0,%1,%2,%3}, {%4,%5,%6,%7}, {%8,%9}, {%0,%1,%2,%3};"
        : "+f"(c[0]), "+f"(c[1]), "+f"(c[2]), "+f"(c[3])
        : "r"(a[0]), "r"(a[1]), "r"(a[2]), "r"(a[3]), "r"(b[0]), "r"(b[1]));
}

// Column permutation: phys col n stored at MMA n-position perm(n) so that
// adjacent nt-fragment pairs hold 4 consecutive phys columns per lane quad.
__device__ __forceinline__ int permN(int n) {
    const int q = (n & 15) >> 2, h = (n >> 1) & 1, b = n & 1;
    return (n & ~15) | (h << 3) | (q << 1) | b;
}

// ---------------- single merged pre-pass ----------------
__global__ void prepass_kernel(const float* __restrict__ x,
                               const float* __restrict__ v) {
    if (blockIdx.x == 0 && threadIdx.x == 0) {
        int col = 0, step = 0, xx, yy, zz;
#define PUT(X, Y, Z) do { d_cell[col*3 + step] = (X) + 3*(Y) + 9*(Z); \
                          step = (step + 1) % 3; } while (0)
        for (xx = 0; xx < 3; xx++) {
            for (yy = 0; yy < 3; yy++) { for (zz = 0; zz < 3; zz++) PUT(xx,yy,zz); col++; }
            for (zz = 0; zz < 3; zz++) { for (yy = 0; yy < 3; yy++) PUT(xx,yy,zz); col++; }
            for (yy = 0; yy < 3; yy++) { zz = yy;     PUT(xx,yy,zz); } col++;
            for (yy = 0; yy < 3; yy++) { zz = 2 - yy; PUT(xx,yy,zz); } col++;
        }
        for (zz = 0; zz < 3; zz++) {
            for (yy = 0; yy < 3; yy++) { for (xx = 0; xx < 3; xx++) PUT(xx,yy,zz); col++; }
            for (yy = 0; yy < 3; yy++) { xx = yy;     PUT(xx,yy,zz); } col++;
            for (yy = 0; yy < 3; yy++) { xx = 2 - yy; PUT(xx,yy,zz); } col++;
        }
        for (yy = 0; yy < 3; yy++) {
            for (zz = 0; zz < 3; zz++) { xx = zz;     PUT(xx,yy,zz); } col++;
            for (zz = 0; zz < 3; zz++) { xx = 2 - zz; PUT(xx,yy,zz); } col++;
        }
        for (xx = 0; xx < 3; xx++) { yy = xx;     zz = xx;     PUT(xx,yy,zz); } col++;
        for (xx = 0; xx < 3; xx++) { yy = 2 - xx; zz = 2 - xx; PUT(xx,yy,zz); } col++;
        for (xx = 0; xx < 3; xx++) { yy = xx;     zz = 2 - xx; PUT(xx,yy,zz); } col++;
        for (xx = 0; xx < 3; xx++) { zz = xx;     yy = 2 - xx; PUT(xx,yy,zz); } col++;
#undef PUT
    }

    if (blockIdx.x < ROWS) {
        const int r = blockIdx.x;
        const float* vb = v + (size_t)r * CH;
        __half* dst = d_vTH + (size_t)r * CH * KTOT;
        for (int u = threadIdx.x; u < CH * (KTOT / 8); u += blockDim.x) {
            const int n  = u & (CH - 1);
            const int k8 = u >> 8;
            uint4 o;
            uint32_t h[4];
#pragma unroll
            for (int p = 0; p < 4; p++) {
                float lo = vb[(size_t)(k8 * 8 + 2 * p + 0) * OUTCOLS + n];
                float hi = vb[(size_t)(k8 * 8 + 2 * p + 1) * OUTCOLS + n];
                h[p] = h2_as_u32(__floats2half2_rn(lo, hi));
            }
            o.x = h[0]; o.y = h[1]; o.z = h[2]; o.w = h[3];
            *reinterpret_cast<uint4*>(dst + (size_t)permN(n) * KTOT + k8 * 8) = o;
        }
    }

    const size_t n8 = (size_t)BATCH * XCOLS / 8;
    const float4* src = reinterpret_cast<const float4*>(x);
    uint4* dst = reinterpret_cast<uint4*>(d_xH);
    for (size_t i = blockIdx.x * (size_t)blockDim.x + threadIdx.x;
         i < n8; i += (size_t)gridDim.x * blockDim.x) {
        float4 a = src[2 * i], b = src[2 * i + 1];
        uint4 o;
        o.x = h2_as_u32(__floats2half2_rn(a.x, a.y));
        o.y = h2_as_u32(__floats2half2_rn(a.z, a.w));
        o.z = h2_as_u32(__floats2half2_rn(b.x, b.y));
        o.w = h2_as_u32(__floats2half2_rn(b.z, b.w));
        dst[i] = o;
    }
}

// ---------------- main GEMM: B fragments register-resident across all tiles ----------------
__global__ void __launch_bounds__(NTHREADS, 1)
tic_mma_kernel(const float* __restrict__ bias, float* __restrict__ out) {
    extern __shared__ char smem[];
    const uint32_t sb = smem_u32(smem);

    const int g    = blockIdx.x >> 1;    // 0..5  batch group
    const int half = blockIdx.x & 1;     // 0..1  column half
    const int r    = blockIdx.y;         // 0..48

    const int nbt   = (g < 2) ? 22 : 21;
    const int btsta = g * 21 + min(g, 2);

    const int tid = threadIdx.x;
    const int wid = tid >> 5, lid = tid & 31;
    const int wr = wid >> 2, wc = wid & 3;          // 2 x 4 warps; warp tile 32x32
    const int grp = lid >> 3, lr = lid & 7;

    const __half* vTb = d_vTH + (size_t)r * CH * KTOT + (size_t)half * BN * KTOT;

    const int ld_row = tid >> 3;          // 0..31
    const int ld_f4  = tid & 7;

    const uint32_t aBase = ((wr * 32 + ((grp & 1) << 3) + lr) * RSH + ((grp >> 1) << 3)) * 2;
    const uint32_t bBase = ((wc * 32 + ((grp & 1) << 3) + lr) * RSH + ((grp >> 1) << 3)) * 2;

    // ---- prologue: B (3 chunks, this half) + A(bt0) into buf0, one commit group ----
#pragma unroll
    for (int c = 0; c < CHUNKS; c++) {
        const uint32_t sB = sb + OFF_B + c * B_CHUNK;
#pragma unroll
        for (int it = 0; it < 4; it++) {
            const int n = ld_row + it * 32;
            cp_async16(sB + n * ROWB + ld_f4 * 16,
                       vTb + (size_t)n * KTOT + c * KC + ld_f4 * 8);
        }
    }
    {
        const __half* xb = d_xH + (size_t)btsta * BM * XCOLS;
#pragma unroll
        for (int c = 0; c < CHUNKS; c++) {
            const uint32_t sA = sb + c * A_CHUNK;
            const int cellbase = d_cell[r * 3 + c] * IN_CH;
#pragma unroll
            for (int it = 0; it < 2; it++) {
                const int row = ld_row + it * 32;
                cp_async16(sA + row * ROWB + ld_f4 * 16,
                           xb + (size_t)row * XCOLS + cellbase + ld_f4 * 8);
            }
        }
    }
    CP_COMMIT();

    const int colw = r * CH + half * BN + wc * 32;
    const int q4   = 4 * (lid & 3);
    const int rbase = wr * 32 + (lid >> 2);

    float4 bj[2];
#pragma unroll
    for (int j = 0; j < 2; j++)
        bj[j] = *reinterpret_cast<const float4*>(bias + colw + 16 * j + q4);

    // ---- wait for B + A0, then load ALL B fragments once (loop-invariant) ----
    CP_WAIT(0);
    __syncthreads();

    uint32_t bfAll[12][4][2];
#pragma unroll
    for (int s = 0; s < 12; s++) {
        const int c = s >> 2, ks = s & 3;
        const uint32_t sB = sb + OFF_B + c * B_CHUNK;
#pragma unroll
        for (int np = 0; np < 2; np++) {
            uint32_t t[4];
            ldmx4(t, sB + bBase + np * 16 * ROWB + ks * 32);
            bfAll[s][np * 2 + 0][0] = t[0]; bfAll[s][np * 2 + 0][1] = t[2];
            bfAll[s][np * 2 + 1][0] = t[1]; bfAll[s][np * 2 + 1][1] = t[3];
        }
    }

    float accA[2][4][4], accB[2][4][4];
    uint32_t af[2][2][4];

#define LDA(S, FB, ABUF) do {                                                  \
        const int c_ = (S) >> 2, ks_ = (S) & 3;                                \
        const uint32_t sA_ = (ABUF) + c_ * A_CHUNK;                            \
        _Pragma("unroll")                                                      \
        for (int mt = 0; mt < 2; mt++)                                         \
            ldmx4(af[FB][mt], sA_ + aBase + mt * 16 * ROWB + ks_ * 32);        \
    } while (0)

    // one bias-added float4 store of PRV tile, K in [0,8)
#define STORE_K(PRV, BTP, K) do {                                              \
        const int j_ = (K) >> 2, mt_ = ((K) >> 1) & 1, hf_ = (K) & 1;          \
        const float* e_ = PRV[mt_][2 * j_];                                    \
        const float* o_ = PRV[mt_][2 * j_ + 1];                                \
        float* p_ = out + (size_t)((BTP) * BM + rbase + mt_ * 16 + hf_ * 8)    \
                          * OUTCOLS + colw + 16 * j_ + q4;                     \
        float4 v_;                                                             \
        if ((hf_) == 0) { v_.x = e_[0] + bj[j_].x; v_.y = e_[1] + bj[j_].y;    \
                          v_.z = o_[0] + bj[j_].z; v_.w = o_[1] + bj[j_].w; }  \
        else            { v_.x = e_[2] + bj[j_].x; v_.y = e_[3] + bj[j_].y;    \
                          v_.z = o_[2] + bj[j_].z; v_.w = o_[3] + bj[j_].w; }  \
        *reinterpret_cast<float4*>(p_) = v_;                                   \
    } while (0)

#define DO_ITER(CUR, PRV, I) do {                                              \
        const int bt_ = btsta + (I);                                           \
        if ((I) > 0) { CP_WAIT(0); __syncthreads(); }                          \
        if ((I) + 1 < nbt) {                                                   \
            const __half* xb_ = d_xH + (size_t)(bt_ + 1) * BM * XCOLS;         \
            const uint32_t bufn_ = (((I) + 1) & 1) * A_BUF;                    \
            _Pragma("unroll")                                                  \
            for (int c = 0; c < CHUNKS; c++) {                                 \
                const uint32_t sA_ = sb + bufn_ + c * A_CHUNK;                 \
                const int cb_ = d_cell[r * 3 + c] * IN_CH;                     \
                _Pragma("unroll")                                              \
                for (int it = 0; it < 2; it++) {                               \
                    const int row_ = ld_row + it * 32;                         \
                    cp_async16(sA_ + row_ * ROWB + ld_f4 * 16,                 \
                               xb_ + (size_t)row_ * XCOLS + cb_ + ld_f4 * 8);  \
                }                                                              \
            }                                                                  \
            CP_COMMIT();                                                       \
        }                                                                      \
        _Pragma("unroll")                                                      \
        for (int a_ = 0; a_ < 2; a_++)                                         \
            _Pragma("unroll")                                                  \
            for (int b_ = 0; b_ < 4; b_++)                                     \
                _Pragma("unroll")                                              \
                for (int q_ = 0; q_ < 4; q_++) CUR[a_][b_][q_] = 0.0f;         \
        const uint32_t abuf_ = sb + ((I) & 1) * A_BUF;                         \
        LDA(0, 0, abuf_);                                                      \
        _Pragma("unroll")                                                      \
        for (int s = 0; s < 12; s++) {                                         \
            if (s < 11) {                                                      \
                if ((s + 1) & 1) LDA(s + 1, 1, abuf_);                         \
                else             LDA(s + 1, 0, abuf_);                         \
            }                                                                  \
            const int cur_ = s & 1;                                            \
            _Pragma("unroll")                                                  \
            for (int mt = 0; mt < 2; mt++)                                     \
                _Pragma("unroll")                                              \
                for (int nt = 0; nt < 4; nt++)                                 \
                    mma_f16(CUR[mt][nt], af[cur_][mt], bfAll[s][nt]);          \
            if ((I) > 0 && s < 8) STORE_K(PRV, bt_ - 1, s);                    \
        }                                                                      \
    } while (0)

    for (int i = 0; i < nbt; i++) {
        if (i & 1) DO_ITER(accB, accA, i);
        else       DO_ITER(accA, accB, i);
    }

    // drain final tile's stores
    {
        const int btl = btsta + nbt - 1;
        if ((nbt - 1) & 1) {
#pragma unroll
            for (int k = 0; k < 8; k++) STORE_K(accB, btl, k);
        } else {
#pragma unroll
            for (int k = 0; k < 8; k++) STORE_K(accA, btl, k);
        }
    }
#undef DO_ITER
#undef STORE_K
#undef LDA
}

extern "C" void kernel_launch(void* const* d_in, const int* in_sizes, int n_in,
                              void* d_out, int out_size) {
    const float* x = nullptr;
    const float* v = nullptr;
    const float* b = nullptr;
    for (int i = 0; i < n_in; i++) {
        if (in_sizes[i] == BATCH * XCOLS)            x = (const float*)d_in[i];
        else if (in_sizes[i] == 3 * IN_CH * OUTCOLS) v = (const float*)d_in[i];
        else if (in_sizes[i] == OUTCOLS)             b = (const float*)d_in[i];
    }
    float* out = (float*)d_out;

    cudaFuncSetAttribute(tic_mma_kernel,
                         cudaFuncAttributeMaxDynamicSharedMemorySize, SMEM_TOTAL);

    prepass_kernel<<<2048, 256>>>(x, v);

    dim3 grid(2 * NGRP, ROWS);   // (12, 49) = 588 CTAs
    tic_mma_kernel<<<grid, NTHREADS, SMEM_TOTAL>>>(b, out);
}